// round 3
// baseline (speedup 1.0000x reference)
#include <cuda_runtime.h>
#include <math.h>

// Problem dims (fixed by reference)
constexpr int BB = 4;
constexpr int SS = 2048;
constexpr int DD = 1024;
constexpr int HH = 1024;

// Scratch (device globals -- no allocation allowed)
__device__ float g_Q[BB * SS * HH];
__device__ float g_K[BB * SS * HH];
__device__ float g_V[BB * SS * HH];
__device__ float g_P[BB * SS * SS];   // scores / probs (in-place softmax)

// ---------------------------------------------------------------------------
// 128x128x8 register-blocked SGEMM, 256 threads, 8x8 micro-tile per thread.
// TRANSB=false: C = A[M,K] * B[K,N] * scale + bias
// TRANSB=true : C = A[M,K] * B[N,K]^T * scale + bias
// All dims assumed divisible by tile sizes (true for this problem).
// ---------------------------------------------------------------------------
template <bool TRANSB>
__global__ __launch_bounds__(256, 2) void sgemm_kernel(
    const float* __restrict__ A, const float* __restrict__ Bm,
    const float* __restrict__ bias, float* __restrict__ C,
    int M, int N, int K, float scale,
    size_t strideA, size_t strideB, size_t strideC)
{
    A  += (size_t)blockIdx.z * strideA;
    Bm += (size_t)blockIdx.z * strideB;
    C  += (size_t)blockIdx.z * strideC;

    __shared__ float As[8][128];
    __shared__ float Bs[8][128];

    const int tid = threadIdx.x;
    const int bm = blockIdx.y * 128;
    const int bn = blockIdx.x * 128;
    const int ty = tid >> 4;    // 0..15
    const int tx = tid & 15;    // 0..15

    // A-tile load mapping: 128 rows x 8 k-cols, each thread one float4
    const int arow = tid >> 1;          // 0..127
    const int acol = (tid & 1) * 4;     // 0 or 4
    // B NN-tile load mapping: 8 k-rows x 128 n-cols
    const int brow = tid >> 5;          // 0..7
    const int bcol = (tid & 31) * 4;    // 0..124

    float acc[8][8];
    #pragma unroll
    for (int i = 0; i < 8; i++)
        #pragma unroll
        for (int j = 0; j < 8; j++) acc[i][j] = 0.0f;

    for (int k0 = 0; k0 < K; k0 += 8) {
        // Load A tile (transpose into As[k][m])
        float4 av = *(const float4*)&A[(size_t)(bm + arow) * K + k0 + acol];
        As[acol + 0][arow] = av.x;
        As[acol + 1][arow] = av.y;
        As[acol + 2][arow] = av.z;
        As[acol + 3][arow] = av.w;

        if (TRANSB) {
            // B is [N, K]; need Bs[k][n]
            float4 bv = *(const float4*)&Bm[(size_t)(bn + arow) * K + k0 + acol];
            Bs[acol + 0][arow] = bv.x;
            Bs[acol + 1][arow] = bv.y;
            Bs[acol + 2][arow] = bv.z;
            Bs[acol + 3][arow] = bv.w;
        } else {
            // B is [K, N]
            float4 bv = *(const float4*)&Bm[(size_t)(k0 + brow) * N + bn + bcol];
            *(float4*)&Bs[brow][bcol] = bv;
        }
        __syncthreads();

        #pragma unroll
        for (int k = 0; k < 8; k++) {
            float4 a0 = *(const float4*)&As[k][ty * 4];
            float4 a1 = *(const float4*)&As[k][64 + ty * 4];
            float4 b0 = *(const float4*)&Bs[k][tx * 4];
            float4 b1 = *(const float4*)&Bs[k][64 + tx * 4];
            float a[8] = {a0.x, a0.y, a0.z, a0.w, a1.x, a1.y, a1.z, a1.w};
            float b[8] = {b0.x, b0.y, b0.z, b0.w, b1.x, b1.y, b1.z, b1.w};
            #pragma unroll
            for (int i = 0; i < 8; i++)
                #pragma unroll
                for (int j = 0; j < 8; j++)
                    acc[i][j] = fmaf(a[i], b[j], acc[i][j]);
        }
        __syncthreads();
    }

    // Epilogue: scale then optional bias, vectorized stores
    #pragma unroll
    for (int i = 0; i < 8; i++) {
        int r = bm + ty * 4 + (i & 3) + (i >> 2) * 64;
        #pragma unroll
        for (int jh = 0; jh < 2; jh++) {
            int c0 = bn + tx * 4 + jh * 64;
            float4 v;
            v.x = acc[i][jh * 4 + 0] * scale;
            v.y = acc[i][jh * 4 + 1] * scale;
            v.z = acc[i][jh * 4 + 2] * scale;
            v.w = acc[i][jh * 4 + 3] * scale;
            if (bias) {
                v.x += bias[c0 + 0];
                v.y += bias[c0 + 1];
                v.z += bias[c0 + 2];
                v.w += bias[c0 + 3];
            }
            *(float4*)&C[(size_t)r * N + c0] = v;
        }
    }
}

// ---------------------------------------------------------------------------
// Row softmax, in place. One block per row (row length SS=2048), 256 threads.
// ---------------------------------------------------------------------------
__global__ __launch_bounds__(256) void softmax_kernel(float* __restrict__ P)
{
    float* p = P + (size_t)blockIdx.x * SS;
    const int t = threadIdx.x;
    __shared__ float red[256];

    float v[8];
    float m = -1e30f;
    #pragma unroll
    for (int i = 0; i < 8; i++) {
        v[i] = p[t + i * 256];
        m = fmaxf(m, v[i]);
    }
    red[t] = m;
    __syncthreads();
    #pragma unroll
    for (int s = 128; s > 0; s >>= 1) {
        if (t < s) red[t] = fmaxf(red[t], red[t + s]);
        __syncthreads();
    }
    m = red[0];
    __syncthreads();

    float sum = 0.0f;
    #pragma unroll
    for (int i = 0; i < 8; i++) {
        v[i] = __expf(v[i] - m);
        sum += v[i];
    }
    red[t] = sum;
    __syncthreads();
    #pragma unroll
    for (int s = 128; s > 0; s >>= 1) {
        if (t < s) red[t] += red[t + s];
        __syncthreads();
    }
    float inv = 1.0f / red[0];

    #pragma unroll
    for (int i = 0; i < 8; i++)
        p[t + i * 256] = v[i] * inv;
}

// ---------------------------------------------------------------------------
extern "C" void kernel_launch(void* const* d_in, const int* in_sizes, int n_in,
                              void* d_out, int out_size)
{
    const float* x  = (const float*)d_in[0];
    const float* Wq = (const float*)d_in[1];
    const float* bq = (const float*)d_in[2];
    const float* Wk = (const float*)d_in[3];
    const float* bk = (const float*)d_in[4];
    const float* Wv = (const float*)d_in[5];
    const float* bv = (const float*)d_in[6];
    float* out = (float*)d_out;

    float *Q, *K, *V, *P;
    cudaGetSymbolAddress((void**)&Q, g_Q);
    cudaGetSymbolAddress((void**)&K, g_K);
    cudaGetSymbolAddress((void**)&V, g_V);
    cudaGetSymbolAddress((void**)&P, g_P);

    dim3 blk(256);
    const int M = BB * SS;  // 8192

    // QKV projections: [8192,1024] x [1024,1024] + bias
    sgemm_kernel<false><<<dim3(HH / 128, M / 128, 1), blk>>>(
        x, Wq, bq, Q, M, HH, DD, 1.0f, 0, 0, 0);
    sgemm_kernel<false><<<dim3(HH / 128, M / 128, 1), blk>>>(
        x, Wk, bk, K, M, HH, DD, 1.0f, 0, 0, 0);
    sgemm_kernel<false><<<dim3(HH / 128, M / 128, 1), blk>>>(
        x, Wv, bv, V, M, HH, DD, 1.0f, 0, 0, 0);

    // Scores: P[b] = Q[b] * K[b]^T * (1/sqrt(H)), batched over z
    sgemm_kernel<true><<<dim3(SS / 128, SS / 128, BB), blk>>>(
        Q, K, nullptr, P, SS, SS, HH, 0.03125f,
        (size_t)SS * HH, (size_t)SS * HH, (size_t)SS * SS);

    // Softmax over rows of P
    softmax_kernel<<<BB * SS, 256>>>(P);

    // Output: out[b] = P[b] * V[b]
    sgemm_kernel<false><<<dim3(HH / 128, SS / 128, BB), blk>>>(
        P, V, nullptr, out, SS, HH, SS, 1.0f,
        (size_t)SS * SS, (size_t)SS * HH, (size_t)SS * HH);
}

// round 7
// speedup vs baseline: 2.8220x; 2.8220x over previous
#include <cuda_runtime.h>
#include <math.h>
#include <stdint.h>

// Problem dims (fixed by reference)
constexpr int BB = 4;
constexpr int SS = 2048;
constexpr int DD = 1024;
constexpr int HH = 1024;

// Scratch (device globals -- no allocation allowed)
__device__ float g_Q[BB * SS * HH];
__device__ float g_K[BB * SS * HH];
__device__ float g_V[BB * SS * HH];
__device__ float g_P[BB * SS * SS];   // scores / probs (in-place softmax)

// ---------------------------------------------------------------------------
// tf32 tensor-core GEMM: 128x128x16 tile, 256 threads (8 warps, 2x4),
// warp tile 64x32, mma.sync.m16n8k8.tf32, cp.async double buffering.
// TRANSB=false: C = A[M,K] * B[K,N] * scale + bias   (B row stride = N)
// TRANSB=true : C = A[M,K] * B[N,K]^T * scale + bias (B row stride = K)
// All dims divisible by tile sizes for this problem.
// ---------------------------------------------------------------------------

__device__ __forceinline__ void cpa16(uint32_t smem_dst, const void* gsrc) {
    asm volatile("cp.async.cg.shared.global [%0], [%1], 16;\n"
                 :: "r"(smem_dst), "l"(gsrc));
}
__device__ __forceinline__ uint32_t tf32_rna(float f) {
    uint32_t r;
    asm("cvt.rna.tf32.f32 %0, %1;\n" : "=r"(r) : "f"(f));
    return r;
}

template <bool TRANSB>
__global__ __launch_bounds__(256, 2) void mm_tf32_kernel(
    const float* __restrict__ A, const float* __restrict__ Bm,
    const float* __restrict__ bias, float* __restrict__ C,
    int M, int N, int K, float scale,
    size_t strideA, size_t strideB, size_t strideC)
{
    constexpr int BK  = 16;
    constexpr int AST = 20;                      // A smem row stride (floats)
    constexpr int BROWS = TRANSB ? 128 : BK;
    constexpr int BST   = TRANSB ? 20  : 136;    // B smem row stride (floats)

    __shared__ float As[2][128 * AST];
    __shared__ float Bs[2][BROWS * BST];

    A  += (size_t)blockIdx.z * strideA;
    Bm += (size_t)blockIdx.z * strideB;
    C  += (size_t)blockIdx.z * strideC;

    const int tid  = threadIdx.x;
    const int lane = tid & 31;
    const int warp = tid >> 5;
    const int wm = warp >> 2;          // 0..1  (64-row slab)
    const int wn = warp & 3;           // 0..3  (32-col slab)
    const int gID = lane >> 2;         // 0..7
    const int tq  = lane & 3;          // 0..3

    const int bm = blockIdx.y * 128;
    const int bn = blockIdx.x * 128;

    // ---- global load mappings ----
    // A tile: 128 rows x 16 k.  Each thread: row=tid>>1, two float4 at cols
    // (tid&1)*8 + {0,4}.
    const int a_row = tid >> 1;
    const int a_col = (tid & 1) * 8;
    const float* gA = A + (size_t)(bm + a_row) * K + a_col;

    // B-NN tile: 16 k-rows x 128 n.  Thread: rows tid>>5 and +8, col (tid&31)*4.
    // B-NT tile: 128 n-rows x 16 k.  Same mapping as A.
    const int bnn_row = tid >> 5;
    const int bnn_col = (tid & 31) * 4;
    const float* gB = TRANSB
        ? (Bm + (size_t)(bn + a_row) * K + a_col)
        : (Bm + (size_t)bnn_row * N + bn + bnn_col);

    // smem byte addresses for the cp.async destinations
    uint32_t sA0 = (uint32_t)__cvta_generic_to_shared(
        &As[0][a_row * AST + a_col]);
    uint32_t sA1 = (uint32_t)__cvta_generic_to_shared(
        &As[1][a_row * AST + a_col]);
    uint32_t sB0, sB1;
    if (TRANSB) {
        sB0 = (uint32_t)__cvta_generic_to_shared(&Bs[0][a_row * BST + a_col]);
        sB1 = (uint32_t)__cvta_generic_to_shared(&Bs[1][a_row * BST + a_col]);
    } else {
        sB0 = (uint32_t)__cvta_generic_to_shared(&Bs[0][bnn_row * BST + bnn_col]);
        sB1 = (uint32_t)__cvta_generic_to_shared(&Bs[1][bnn_row * BST + bnn_col]);
    }

    float acc[4][4][4];
    #pragma unroll
    for (int mi = 0; mi < 4; mi++)
        #pragma unroll
        for (int ni = 0; ni < 4; ni++)
            #pragma unroll
            for (int q = 0; q < 4; q++) acc[mi][ni][q] = 0.0f;

    const int ntiles = K / BK;

    auto load_tile = [&](int t, int buf) {
        uint32_t sa = buf ? sA1 : sA0;
        uint32_t sb = buf ? sB1 : sB0;
        const float* ga = gA + t * BK;
        cpa16(sa,      ga);
        cpa16(sa + 16, ga + 4);
        if (TRANSB) {
            const float* gb = gB + t * BK;
            cpa16(sb,      gb);
            cpa16(sb + 16, gb + 4);
        } else {
            const float* gb = gB + (size_t)t * BK * N;
            cpa16(sb,                       gb);
            cpa16(sb + 8 * BST * 4,         gb + (size_t)8 * N);
        }
    };

    load_tile(0, 0);
    asm volatile("cp.async.commit_group;\n" ::);

    int buf = 0;
    for (int t = 0; t < ntiles; t++) {
        if (t + 1 < ntiles) load_tile(t + 1, buf ^ 1);
        asm volatile("cp.async.commit_group;\n" ::);
        asm volatile("cp.async.wait_group 1;\n" ::);
        __syncthreads();

        const float* as = As[buf];
        const float* bs = Bs[buf];

        #pragma unroll
        for (int ks = 0; ks < 2; ks++) {
            const int k0 = ks * 8;
            uint32_t af[4][4], bf[4][2];
            #pragma unroll
            for (int mi = 0; mi < 4; mi++) {
                const int r = wm * 64 + mi * 16 + gID;
                af[mi][0] = tf32_rna(as[(r    ) * AST + k0 + tq    ]);
                af[mi][1] = tf32_rna(as[(r + 8) * AST + k0 + tq    ]);
                af[mi][2] = tf32_rna(as[(r    ) * AST + k0 + tq + 4]);
                af[mi][3] = tf32_rna(as[(r + 8) * AST + k0 + tq + 4]);
            }
            #pragma unroll
            for (int ni = 0; ni < 4; ni++) {
                const int n = wn * 32 + ni * 8 + gID;
                if (TRANSB) {
                    bf[ni][0] = tf32_rna(bs[n * BST + k0 + tq    ]);
                    bf[ni][1] = tf32_rna(bs[n * BST + k0 + tq + 4]);
                } else {
                    bf[ni][0] = tf32_rna(bs[(k0 + tq    ) * BST + n]);
                    bf[ni][1] = tf32_rna(bs[(k0 + tq + 4) * BST + n]);
                }
            }
            #pragma unroll
            for (int mi = 0; mi < 4; mi++)
                #pragma unroll
                for (int ni = 0; ni < 4; ni++) {
                    asm volatile(
                        "mma.sync.aligned.m16n8k8.row.col.f32.tf32.tf32.f32 "
                        "{%0,%1,%2,%3}, {%4,%5,%6,%7}, {%8,%9}, {%0,%1,%2,%3};\n"
                        : "+f"(acc[mi][ni][0]), "+f"(acc[mi][ni][1]),
                          "+f"(acc[mi][ni][2]), "+f"(acc[mi][ni][3])
                        : "r"(af[mi][0]), "r"(af[mi][1]),
                          "r"(af[mi][2]), "r"(af[mi][3]),
                          "r"(bf[ni][0]), "r"(bf[ni][1]));
                }
        }
        __syncthreads();
        buf ^= 1;
    }

    // ---- epilogue: scale, optional bias, store ----
    #pragma unroll
    for (int mi = 0; mi < 4; mi++) {
        const int r0 = bm + wm * 64 + mi * 16 + gID;
        #pragma unroll
        for (int ni = 0; ni < 4; ni++) {
            const int c = bn + wn * 32 + ni * 8 + tq * 2;
            float b0 = 0.0f, b1 = 0.0f;
            if (bias) { b0 = bias[c]; b1 = bias[c + 1]; }
            float2 v0, v1;
            v0.x = acc[mi][ni][0] * scale + b0;
            v0.y = acc[mi][ni][1] * scale + b1;
            v1.x = acc[mi][ni][2] * scale + b0;
            v1.y = acc[mi][ni][3] * scale + b1;
            *(float2*)&C[(size_t)r0 * N + c]       = v0;
            *(float2*)&C[(size_t)(r0 + 8) * N + c] = v1;
        }
    }
}

// ---------------------------------------------------------------------------
// Row softmax, in place. One block per row (row length SS=2048), 256 threads.
// ---------------------------------------------------------------------------
__global__ __launch_bounds__(256) void softmax_kernel(float* __restrict__ P)
{
    float* p = P + (size_t)blockIdx.x * SS;
    const int t = threadIdx.x;
    __shared__ float red[256];

    float v[8];
    float m = -1e30f;
    #pragma unroll
    for (int i = 0; i < 8; i++) {
        v[i] = p[t + i * 256];
        m = fmaxf(m, v[i]);
    }
    red[t] = m;
    __syncthreads();
    #pragma unroll
    for (int s = 128; s > 0; s >>= 1) {
        if (t < s) red[t] = fmaxf(red[t], red[t + s]);
        __syncthreads();
    }
    m = red[0];
    __syncthreads();

    float sum = 0.0f;
    #pragma unroll
    for (int i = 0; i < 8; i++) {
        v[i] = __expf(v[i] - m);
        sum += v[i];
    }
    red[t] = sum;
    __syncthreads();
    #pragma unroll
    for (int s = 128; s > 0; s >>= 1) {
        if (t < s) red[t] += red[t + s];
        __syncthreads();
    }
    float inv = 1.0f / red[0];

    #pragma unroll
    for (int i = 0; i < 8; i++)
        p[t + i * 256] = v[i] * inv;
}

// ---------------------------------------------------------------------------
extern "C" void kernel_launch(void* const* d_in, const int* in_sizes, int n_in,
                              void* d_out, int out_size)
{
    const float* x  = (const float*)d_in[0];
    const float* Wq = (const float*)d_in[1];
    const float* bq = (const float*)d_in[2];
    const float* Wk = (const float*)d_in[3];
    const float* bk = (const float*)d_in[4];
    const float* Wv = (const float*)d_in[5];
    const float* bv = (const float*)d_in[6];
    float* out = (float*)d_out;

    float *Q, *K, *V, *P;
    cudaGetSymbolAddress((void**)&Q, g_Q);
    cudaGetSymbolAddress((void**)&K, g_K);
    cudaGetSymbolAddress((void**)&V, g_V);
    cudaGetSymbolAddress((void**)&P, g_P);

    dim3 blk(256);
    const int M = BB * SS;  // 8192

    // QKV projections: [8192,1024] x [1024,1024] + bias
    mm_tf32_kernel<false><<<dim3(HH / 128, M / 128, 1), blk>>>(
        x, Wq, bq, Q, M, HH, DD, 1.0f, 0, 0, 0);
    mm_tf32_kernel<false><<<dim3(HH / 128, M / 128, 1), blk>>>(
        x, Wk, bk, K, M, HH, DD, 1.0f, 0, 0, 0);
    mm_tf32_kernel<false><<<dim3(HH / 128, M / 128, 1), blk>>>(
        x, Wv, bv, V, M, HH, DD, 1.0f, 0, 0, 0);

    // Scores: P[b] = Q[b] * K[b]^T * (1/sqrt(H)), batched over z
    mm_tf32_kernel<true><<<dim3(SS / 128, SS / 128, BB), blk>>>(
        Q, K, nullptr, P, SS, SS, HH, 0.03125f,
        (size_t)SS * HH, (size_t)SS * HH, (size_t)SS * SS);

    // Softmax over rows of P
    softmax_kernel<<<BB * SS, 256>>>(P);

    // Output: out[b] = P[b] * V[b]
    mm_tf32_kernel<false><<<dim3(HH / 128, SS / 128, BB), blk>>>(
        P, V, nullptr, out, SS, HH, SS, 1.0f,
        (size_t)SS * SS, (size_t)SS * HH, (size_t)SS * HH);
}